// round 4
// baseline (speedup 1.0000x reference)
#include <cuda_runtime.h>

#define HH 128           // hidden dim
#define AA 8             // heads
#define DD 16            // head dim
#define MAXN 50048
#define MAXE 800000
#define BM 64
#define BK 32
#define XS_STRIDE 68
#define SCAN_BLK 1024
#define MAX_SCAN_BLOCKS 64

// ---------------- device scratch (no allocations allowed) ----------------
__device__ __align__(128) float g_P[3][(size_t)MAXN * HH];   // projected Qn,Kn,Vn
__device__ __align__(128) float g_WT[3][HH * HH];            // W transposed (k-major)
__device__ int g_count[MAXN];
__device__ int g_off[MAXN + 1];
__device__ int g_cursor[MAXN];
__device__ int g_eid[MAXE];
__device__ int g_bsum[MAX_SCAN_BLOCKS];
__device__ int g_bbase[MAX_SCAN_BLOCKS];

// ---------------- packed f32x2 helpers (Blackwell FFMA2) ----------------
__device__ __forceinline__ unsigned long long fma2(unsigned long long a,
                                                   unsigned long long b,
                                                   unsigned long long c) {
    unsigned long long d;
    asm("fma.rn.f32x2 %0, %1, %2, %3;" : "=l"(d) : "l"(a), "l"(b), "l"(c));
    return d;
}
__device__ __forceinline__ unsigned long long pack2(float lo, float hi) {
    unsigned long long d;
    asm("mov.b64 %0, {%1, %2};" : "=l"(d) : "f"(lo), "f"(hi));
    return d;
}
__device__ __forceinline__ float2 unpack2(unsigned long long v) {
    float2 r;
    asm("mov.b64 {%0, %1}, %2;" : "=f"(r.x), "=f"(r.y) : "l"(v));
    return r;
}

// ---------------- K0: transpose weights to k-major ----------------
__global__ void wt_kernel(const float* __restrict__ Wq,
                          const float* __restrict__ Wk,
                          const float* __restrict__ Wv) {
    int z = blockIdx.y;
    const float* W = (z == 0) ? Wq : (z == 1) ? Wk : Wv;
    int idx = blockIdx.x * 256 + threadIdx.x;
    if (idx < HH * HH) {
        int o = idx >> 7;
        int kk = idx & 127;
        g_WT[z][kk * HH + o] = W[idx];   // WT[k][o] = W[o][k]
    }
}

// ---------------- CSR build ----------------
__global__ void zero_kernel(int n) {
    int i = blockIdx.x * 256 + threadIdx.x;
    if (i < n) g_count[i] = 0;
}
__global__ void hist_kernel(const int* __restrict__ qi, int e) {
    int i = blockIdx.x * 256 + threadIdx.x;
    if (i < e) atomicAdd(&g_count[qi[i]], 1);
}

// Phase 1: per-block exclusive scan (warp shuffle + smem warp totals).
// Writes exclusive intra-block prefix to g_off[i], block total to g_bsum[b].
__global__ void __launch_bounds__(SCAN_BLK) scan1_kernel(int n) {
    __shared__ int wsum[32];
    int i = blockIdx.x * SCAN_BLK + threadIdx.x;
    int lane = threadIdx.x & 31;
    int wid = threadIdx.x >> 5;
    int v = (i < n) ? g_count[i] : 0;
    // inclusive warp scan
    int x = v;
#pragma unroll
    for (int d = 1; d < 32; d <<= 1) {
        int y = __shfl_up_sync(0xffffffffu, x, d);
        if (lane >= d) x += y;
    }
    if (lane == 31) wsum[wid] = x;
    __syncthreads();
    if (wid == 0) {
        int s = wsum[lane];
#pragma unroll
        for (int d = 1; d < 32; d <<= 1) {
            int y = __shfl_up_sync(0xffffffffu, s, d);
            if (lane >= d) s += y;
        }
        wsum[lane] = s;
    }
    __syncthreads();
    int base = (wid > 0) ? wsum[wid - 1] : 0;
    int incl = base + x;
    if (i < n) g_off[i] = incl - v;              // exclusive prefix in-block
    if (threadIdx.x == SCAN_BLK - 1) g_bsum[blockIdx.x] = incl;  // block total
}

// Phase 2: scan the (<=64) block totals; also publish grand total as g_off[n].
__global__ void scan2_kernel(int nb, int n) {
    __shared__ int s[MAX_SCAN_BLOCKS];
    int t = threadIdx.x;
    int v = (t < nb) ? g_bsum[t] : 0;
    s[t] = v;
    __syncthreads();
#pragma unroll
    for (int d = 1; d < MAX_SCAN_BLOCKS; d <<= 1) {
        int y = (t >= d) ? s[t - d] : 0;
        __syncthreads();
        s[t] += y;
        __syncthreads();
    }
    if (t < nb) g_bbase[t] = s[t] - v;           // exclusive
    if (t == nb - 1) g_off[n] = s[t];            // grand total (== E)
}

// Phase 3: add block bases; init cursors.
__global__ void __launch_bounds__(SCAN_BLK) scan3_kernel(int n) {
    int i = blockIdx.x * SCAN_BLK + threadIdx.x;
    if (i < n) {
        int o = g_off[i] + g_bbase[blockIdx.x];
        g_off[i] = o;
        g_cursor[i] = o;
    }
}

__global__ void scatter_kernel(const int* __restrict__ qi, int e) {
    int i = blockIdx.x * 256 + threadIdx.x;
    if (i < e) {
        int pos = atomicAdd(&g_cursor[qi[i]], 1);
        g_eid[pos] = i;
    }
}

// ---------------- K1: projection GEMM, Y = X @ W^T + b ----------------
__global__ void __launch_bounds__(256) proj_gemm(
    const float* __restrict__ Xq, const float* __restrict__ Xk,
    const float* __restrict__ Xv,
    const float* __restrict__ Bq, const float* __restrict__ Bk,
    const float* __restrict__ Bv, int M) {
    __shared__ __align__(16) float Ws[BK * HH];         // Ws[k][o]
    __shared__ __align__(16) float Xs[BK * XS_STRIDE];  // Xs[k][row], padded

    int z = blockIdx.z;
    const float* X = (z == 0) ? Xq : (z == 1) ? Xk : Xv;
    const float* B = (z == 0) ? Bq : (z == 1) ? Bk : Bv;
    const float* WT = g_WT[z];
    float* Y = g_P[z];

    int t = threadIdx.x;
    int m0 = blockIdx.x * BM;
    int tx = t & 31;
    int ty = t >> 5;
    int c0 = tx * 4;   // 4 output cols
    int r0 = ty * 8;   // 8 output rows

    unsigned long long acc[4][4];
#pragma unroll
    for (int p = 0; p < 4; p++)
#pragma unroll
        for (int c = 0; c < 4; c++) acc[p][c] = 0ull;

    for (int kt = 0; kt < HH; kt += BK) {
        __syncthreads();
        {
            const float4* src = (const float4*)(WT + kt * HH);
            float4* dst = (float4*)Ws;
#pragma unroll
            for (int i = 0; i < 4; i++) dst[t + i * 256] = src[t + i * 256];
        }
        {
#pragma unroll
            for (int i = 0; i < 2; i++) {
                int idx = t + i * 256;      // 0..511
                int row = idx >> 3;         // 0..63
                int c4 = idx & 7;           // float4 within 32 cols
                int gm = m0 + row;
                float4 xv = make_float4(0.f, 0.f, 0.f, 0.f);
                if (gm < M) xv = ((const float4*)X)[gm * (HH / 4) + (kt >> 2) + c4];
                int kk = c4 * 4;
                Xs[(kk + 0) * XS_STRIDE + row] = xv.x;
                Xs[(kk + 1) * XS_STRIDE + row] = xv.y;
                Xs[(kk + 2) * XS_STRIDE + row] = xv.z;
                Xs[(kk + 3) * XS_STRIDE + row] = xv.w;
            }
        }
        __syncthreads();

#pragma unroll
        for (int kk = 0; kk < BK; kk++) {
            float4 w4 = *(const float4*)(Ws + kk * HH + c0);
            unsigned long long b0 = pack2(w4.x, w4.x);
            unsigned long long b1 = pack2(w4.y, w4.y);
            unsigned long long b2 = pack2(w4.z, w4.z);
            unsigned long long b3 = pack2(w4.w, w4.w);
            const float* xp = Xs + kk * XS_STRIDE + r0;
            ulonglong2 aA = *(const ulonglong2*)(xp);       // rows r0..r0+3
            ulonglong2 aB = *(const ulonglong2*)(xp + 4);   // rows r0+4..r0+7
            unsigned long long a0 = aA.x, a1 = aA.y, a2 = aB.x, a3 = aB.y;
            acc[0][0] = fma2(a0, b0, acc[0][0]);
            acc[0][1] = fma2(a0, b1, acc[0][1]);
            acc[0][2] = fma2(a0, b2, acc[0][2]);
            acc[0][3] = fma2(a0, b3, acc[0][3]);
            acc[1][0] = fma2(a1, b0, acc[1][0]);
            acc[1][1] = fma2(a1, b1, acc[1][1]);
            acc[1][2] = fma2(a1, b2, acc[1][2]);
            acc[1][3] = fma2(a1, b3, acc[1][3]);
            acc[2][0] = fma2(a2, b0, acc[2][0]);
            acc[2][1] = fma2(a2, b1, acc[2][1]);
            acc[2][2] = fma2(a2, b2, acc[2][2]);
            acc[2][3] = fma2(a2, b3, acc[2][3]);
            acc[3][0] = fma2(a3, b0, acc[3][0]);
            acc[3][1] = fma2(a3, b1, acc[3][1]);
            acc[3][2] = fma2(a3, b2, acc[3][2]);
            acc[3][3] = fma2(a3, b3, acc[3][3]);
        }
    }

    float4 bias = *(const float4*)(B + c0);
#pragma unroll
    for (int p = 0; p < 4; p++) {
        float2 v0 = unpack2(acc[p][0]);
        float2 v1 = unpack2(acc[p][1]);
        float2 v2 = unpack2(acc[p][2]);
        float2 v3 = unpack2(acc[p][3]);
        int gm = m0 + r0 + 2 * p;
        if (gm < M) {
            float4 o0 = make_float4(v0.x + bias.x, v1.x + bias.y,
                                    v2.x + bias.z, v3.x + bias.w);
            *(float4*)(Y + (size_t)gm * HH + c0) = o0;
        }
        if (gm + 1 < M) {
            float4 o1 = make_float4(v0.y + bias.x, v1.y + bias.y,
                                    v2.y + bias.z, v3.y + bias.w);
            *(float4*)(Y + (size_t)(gm + 1) * HH + c0) = o1;
        }
    }
}

// ---------------- K3: warp-per-node attention (fused softmax) ----------------
__global__ void __launch_bounds__(256) attn_kernel(const int* __restrict__ ki,
                                                   float* __restrict__ out,
                                                   int n) {
    int warp = (blockIdx.x * blockDim.x + threadIdx.x) >> 5;
    int lane = threadIdx.x & 31;
    if (warp >= n) return;
    int i = warp;
    const float* Qn = g_P[0];
    const float* Kn = g_P[1];
    const float* Vn = g_P[2];

    float4 qv = ((const float4*)(Qn + (size_t)i * HH))[lane];
    int beg = g_off[i];
    int end = g_off[i + 1];

    float4 acc = make_float4(0.f, 0.f, 0.f, 0.f);
    float den = 0.f;

    int kn_next = 0;
    if (beg < end) kn_next = ki[g_eid[beg]];

    for (int j = beg; j < end; j++) {
        int kn = kn_next;
        if (j + 1 < end) kn_next = ki[g_eid[j + 1]];
        float4 k4 = ((const float4*)(Kn + (size_t)kn * HH))[lane];
        float4 v4 = ((const float4*)(Vn + (size_t)kn * HH))[lane];
        float s = qv.x * k4.x + qv.y * k4.y + qv.z * k4.z + qv.w * k4.w;
        s += __shfl_xor_sync(0xffffffffu, s, 1);
        s += __shfl_xor_sync(0xffffffffu, s, 2);   // per-head dot over 16 dims
        float ex = __expf(s * 0.25f);               // / sqrt(D), D=16
        den += ex;
        acc.x += ex * v4.x;
        acc.y += ex * v4.y;
        acc.z += ex * v4.z;
        acc.w += ex * v4.w;
    }

    float inv = (end > beg) ? (1.f / den) : 0.f;
    float4 o = make_float4(acc.x * inv, acc.y * inv, acc.z * inv, acc.w * inv);
    ((float4*)(out + (size_t)i * HH))[lane] = o;
}

// ---------------- launch ----------------
extern "C" void kernel_launch(void* const* d_in, const int* in_sizes, int n_in,
                              void* d_out, int out_size) {
    const float* q = (const float*)d_in[0];
    const float* k = (const float*)d_in[1];
    const float* v = (const float*)d_in[2];
    const float* Wq = (const float*)d_in[3];
    const float* bq = (const float*)d_in[4];
    const float* Wk = (const float*)d_in[5];
    const float* bk = (const float*)d_in[6];
    const float* Wv = (const float*)d_in[7];
    const float* bv = (const float*)d_in[8];
    const int* qi = (const int*)d_in[9];
    const int* ki = (const int*)d_in[10];

    int Nn = in_sizes[0] / HH;   // 50000
    int E = in_sizes[9];         // 800000
    float* out = (float*)d_out;

    // weight transpose
    wt_kernel<<<dim3(64, 3), 256>>>(Wq, Wk, Wv);

    // CSR build over destination nodes (parallel 3-phase scan)
    int nb = (Nn + SCAN_BLK - 1) / SCAN_BLK;     // 49 for N=50000
    zero_kernel<<<(Nn + 255) / 256, 256>>>(Nn);
    hist_kernel<<<(E + 255) / 256, 256>>>(qi, E);
    scan1_kernel<<<nb, SCAN_BLK>>>(Nn);
    scan2_kernel<<<1, MAX_SCAN_BLOCKS>>>(nb, Nn);
    scan3_kernel<<<nb, SCAN_BLK>>>(Nn);
    scatter_kernel<<<(E + 255) / 256, 256>>>(qi, E);

    // per-node projections Qn/Kn/Vn
    proj_gemm<<<dim3((Nn + BM - 1) / BM, 1, 3), 256>>>(q, k, v, bq, bk, bv, Nn);

    // fused gather + scores + softmax + aggregate
    attn_kernel<<<((long long)Nn * 32 + 255) / 256, 256>>>(ki, out, Nn);
}

// round 7
// speedup vs baseline: 1.4732x; 1.4732x over previous
#include <cuda_runtime.h>

#define HH 128           // hidden dim
#define MAXN 50048
#define MAXE 800000
#define BM 128
#define BK 32
#define XS_STRIDE 132    // BM + 4 pad (16B-aligned row stride: 528B)
#define SCAN_BLK 1024
#define MAX_SCAN_BLOCKS 64

// ---------------- device scratch (no allocations allowed) ----------------
__device__ __align__(128) float g_P[3][(size_t)MAXN * HH];   // projected Qn,Kn,Vn
__device__ __align__(128) float g_WT[3][HH * HH];            // W transposed (k-major)
__device__ int g_count[MAXN];
__device__ int g_off[MAXN + 1];
__device__ int g_cursor[MAXN];
__device__ int g_kn[MAXE];        // CSR payload: source node id (ki[e]) directly
__device__ int g_bsum[MAX_SCAN_BLOCKS];
__device__ int g_bbase[MAX_SCAN_BLOCKS];

// ---------------- packed f32x2 helpers (Blackwell FFMA2) ----------------
__device__ __forceinline__ unsigned long long fma2(unsigned long long a,
                                                   unsigned long long b,
                                                   unsigned long long c) {
    unsigned long long d;
    asm("fma.rn.f32x2 %0, %1, %2, %3;" : "=l"(d) : "l"(a), "l"(b), "l"(c));
    return d;
}
__device__ __forceinline__ unsigned long long pack2(float lo, float hi) {
    unsigned long long d;
    asm("mov.b64 %0, {%1, %2};" : "=l"(d) : "f"(lo), "f"(hi));
    return d;
}
__device__ __forceinline__ float2 unpack2(unsigned long long v) {
    float2 r;
    asm("mov.b64 {%0, %1}, %2;" : "=f"(r.x), "=f"(r.y) : "l"(v));
    return r;
}

// ---------------- K0: transpose weights to k-major ----------------
__global__ void wt_kernel(const float* __restrict__ Wq,
                          const float* __restrict__ Wk,
                          const float* __restrict__ Wv) {
    int z = blockIdx.y;
    const float* W = (z == 0) ? Wq : (z == 1) ? Wk : Wv;
    int idx = blockIdx.x * 256 + threadIdx.x;
    if (idx < HH * HH) {
        int o = idx >> 7;
        int kk = idx & 127;
        g_WT[z][kk * HH + o] = W[idx];   // WT[k][o] = W[o][k]
    }
}

// ---------------- CSR build ----------------
__global__ void zero_kernel(int n) {
    int i = blockIdx.x * 256 + threadIdx.x;
    if (i < n) g_count[i] = 0;
}
__global__ void hist_kernel(const int* __restrict__ qi, int e) {
    int i = blockIdx.x * 256 + threadIdx.x;
    if (i < e) atomicAdd(&g_count[qi[i]], 1);
}
__global__ void __launch_bounds__(SCAN_BLK) scan1_kernel(int n) {
    __shared__ int wsum[32];
    int i = blockIdx.x * SCAN_BLK + threadIdx.x;
    int lane = threadIdx.x & 31;
    int wid = threadIdx.x >> 5;
    int v = (i < n) ? g_count[i] : 0;
    int x = v;
#pragma unroll
    for (int d = 1; d < 32; d <<= 1) {
        int y = __shfl_up_sync(0xffffffffu, x, d);
        if (lane >= d) x += y;
    }
    if (lane == 31) wsum[wid] = x;
    __syncthreads();
    if (wid == 0) {
        int s = wsum[lane];
#pragma unroll
        for (int d = 1; d < 32; d <<= 1) {
            int y = __shfl_up_sync(0xffffffffu, s, d);
            if (lane >= d) s += y;
        }
        wsum[lane] = s;
    }
    __syncthreads();
    int base = (wid > 0) ? wsum[wid - 1] : 0;
    int incl = base + x;
    if (i < n) g_off[i] = incl - v;
    if (threadIdx.x == SCAN_BLK - 1) g_bsum[blockIdx.x] = incl;
}
__global__ void scan2_kernel(int nb, int n) {
    __shared__ int s[MAX_SCAN_BLOCKS];
    int t = threadIdx.x;
    int v = (t < nb) ? g_bsum[t] : 0;
    s[t] = v;
    __syncthreads();
#pragma unroll
    for (int d = 1; d < MAX_SCAN_BLOCKS; d <<= 1) {
        int y = (t >= d) ? s[t - d] : 0;
        __syncthreads();
        s[t] += y;
        __syncthreads();
    }
    if (t < nb) g_bbase[t] = s[t] - v;
    if (t == nb - 1) g_off[n] = s[t];
}
__global__ void __launch_bounds__(SCAN_BLK) scan3_kernel(int n) {
    int i = blockIdx.x * SCAN_BLK + threadIdx.x;
    if (i < n) {
        int o = g_off[i] + g_bbase[blockIdx.x];
        g_off[i] = o;
        g_cursor[i] = o;
    }
}
// Scatter the SOURCE node id (not the edge id): attn needs only ki[e].
__global__ void scatter_kernel(const int* __restrict__ qi,
                               const int* __restrict__ ki, int e) {
    int i = blockIdx.x * 256 + threadIdx.x;
    if (i < e) {
        int pos = atomicAdd(&g_cursor[qi[i]], 1);
        g_kn[pos] = ki[i];
    }
}

// ---------------- K1: projection GEMM, Y = X @ W^T + b ----------------
// BM=128 rows x 128 cols per 256-thread block. Per thread: 16 rows x 4 cols,
// accumulated as 8x4 f32x2 (row pairs). W reads conflict-free, X broadcast.
__global__ void __launch_bounds__(256, 2) proj_gemm(
    const float* __restrict__ Xq, const float* __restrict__ Xk,
    const float* __restrict__ Xv,
    const float* __restrict__ Bq, const float* __restrict__ Bk,
    const float* __restrict__ Bv, int M) {
    __shared__ __align__(16) float Ws[BK * HH];         // Ws[k][o]
    __shared__ __align__(16) float Xs[BK * XS_STRIDE];  // Xs[k][row], padded

    int z = blockIdx.z;
    const float* X = (z == 0) ? Xq : (z == 1) ? Xk : Xv;
    const float* B = (z == 0) ? Bq : (z == 1) ? Bk : Bv;
    const float* WT = g_WT[z];
    float* Y = g_P[z];

    int t = threadIdx.x;
    int m0 = blockIdx.x * BM;
    int tx = t & 31;
    int ty = t >> 5;
    int c0 = tx * 4;    // 4 output cols
    int r0 = ty * 16;   // 16 output rows

    unsigned long long acc[8][4];
#pragma unroll
    for (int p = 0; p < 8; p++)
#pragma unroll
        for (int c = 0; c < 4; c++) acc[p][c] = 0ull;

    for (int kt = 0; kt < HH; kt += BK) {
        __syncthreads();
        // W tile: 4096 floats, straight float4 copy
        {
            const float4* src = (const float4*)(WT + kt * HH);
            float4* dst = (float4*)Ws;
#pragma unroll
            for (int i = 0; i < 4; i++) dst[t + i * 256] = src[t + i * 256];
        }
        // X tile: 128 rows x 32 cols, coalesced float4 loads, transposed scatter
        {
#pragma unroll
            for (int i = 0; i < 4; i++) {
                int idx = t + i * 256;      // 0..1023
                int row = idx >> 3;         // 0..127
                int c4 = idx & 7;           // float4 within 32 cols
                int gm = m0 + row;
                float4 xv = make_float4(0.f, 0.f, 0.f, 0.f);
                if (gm < M) xv = ((const float4*)X)[gm * (HH / 4) + (kt >> 2) + c4];
                int kk = c4 * 4;
                Xs[(kk + 0) * XS_STRIDE + row] = xv.x;
                Xs[(kk + 1) * XS_STRIDE + row] = xv.y;
                Xs[(kk + 2) * XS_STRIDE + row] = xv.z;
                Xs[(kk + 3) * XS_STRIDE + row] = xv.w;
            }
        }
        __syncthreads();

#pragma unroll 4
        for (int kk = 0; kk < BK; kk++) {
            float4 w4 = *(const float4*)(Ws + kk * HH + c0);
            unsigned long long b0 = pack2(w4.x, w4.x);
            unsigned long long b1 = pack2(w4.y, w4.y);
            unsigned long long b2 = pack2(w4.z, w4.z);
            unsigned long long b3 = pack2(w4.w, w4.w);
            const float* xp = Xs + kk * XS_STRIDE + r0;
            ulonglong2 aA = *(const ulonglong2*)(xp);        // rows r0..+3
            ulonglong2 aB = *(const ulonglong2*)(xp + 4);    // rows +4..+7
            ulonglong2 aC = *(const ulonglong2*)(xp + 8);    // rows +8..+11
            ulonglong2 aD = *(const ulonglong2*)(xp + 12);   // rows +12..+15
            unsigned long long a[8] = {aA.x, aA.y, aB.x, aB.y,
                                       aC.x, aC.y, aD.x, aD.y};
#pragma unroll
            for (int p = 0; p < 8; p++) {
                acc[p][0] = fma2(a[p], b0, acc[p][0]);
                acc[p][1] = fma2(a[p], b1, acc[p][1]);
                acc[p][2] = fma2(a[p], b2, acc[p][2]);
                acc[p][3] = fma2(a[p], b3, acc[p][3]);
            }
        }
    }

    float4 bias = *(const float4*)(B + c0);
#pragma unroll
    for (int p = 0; p < 8; p++) {
        float2 v0 = unpack2(acc[p][0]);
        float2 v1 = unpack2(acc[p][1]);
        float2 v2 = unpack2(acc[p][2]);
        float2 v3 = unpack2(acc[p][3]);
        int gm = m0 + r0 + 2 * p;
        if (gm < M) {
            float4 o0 = make_float4(v0.x + bias.x, v1.x + bias.y,
                                    v2.x + bias.z, v3.x + bias.w);
            *(float4*)(Y + (size_t)gm * HH + c0) = o0;
        }
        if (gm + 1 < M) {
            float4 o1 = make_float4(v0.y + bias.x, v1.y + bias.y,
                                    v2.y + bias.z, v3.y + bias.w);
            *(float4*)(Y + (size_t)(gm + 1) * HH + c0) = o1;
        }
    }
}

// ---------------- K3: warp-per-node attention (fused softmax) ----------------
// lane l owns dims [4l, 4l+4); head = l>>2 (D=16 => 4 lanes/head).
// ctx[i] = (sum_e ex_e * V_e) / (sum_e ex_e)  -- division deferred.
// Unrolled by 2: 4 independent 512B row loads in flight per iteration.
__global__ void __launch_bounds__(256) attn_kernel(float* __restrict__ out,
                                                   int n) {
    int warp = (blockIdx.x * blockDim.x + threadIdx.x) >> 5;
    int lane = threadIdx.x & 31;
    if (warp >= n) return;
    int i = warp;
    const float* Qn = g_P[0];
    const float* Kn = g_P[1];
    const float* Vn = g_P[2];

    float4 qv = ((const float4*)(Qn + (size_t)i * HH))[lane];
    int beg = g_off[i];
    int end = g_off[i + 1];

    float4 acc = make_float4(0.f, 0.f, 0.f, 0.f);
    float den = 0.f;

    int j = beg;
    for (; j + 1 < end; j += 2) {
        int kn0 = g_kn[j];
        int kn1 = g_kn[j + 1];
        float4 k0 = ((const float4*)(Kn + (size_t)kn0 * HH))[lane];
        float4 k1 = ((const float4*)(Kn + (size_t)kn1 * HH))[lane];
        float4 v0 = ((const float4*)(Vn + (size_t)kn0 * HH))[lane];
        float4 v1 = ((const float4*)(Vn + (size_t)kn1 * HH))[lane];
        float s0 = qv.x * k0.x + qv.y * k0.y + qv.z * k0.z + qv.w * k0.w;
        float s1 = qv.x * k1.x + qv.y * k1.y + qv.z * k1.z + qv.w * k1.w;
        s0 += __shfl_xor_sync(0xffffffffu, s0, 1);
        s1 += __shfl_xor_sync(0xffffffffu, s1, 1);
        s0 += __shfl_xor_sync(0xffffffffu, s0, 2);
        s1 += __shfl_xor_sync(0xffffffffu, s1, 2);
        float ex0 = __expf(s0 * 0.25f);
        float ex1 = __expf(s1 * 0.25f);
        den += ex0 + ex1;
        acc.x += ex0 * v0.x + ex1 * v1.x;
        acc.y += ex0 * v0.y + ex1 * v1.y;
        acc.z += ex0 * v0.z + ex1 * v1.z;
        acc.w += ex0 * v0.w + ex1 * v1.w;
    }
    if (j < end) {
        int kn = g_kn[j];
        float4 k4 = ((const float4*)(Kn + (size_t)kn * HH))[lane];
        float4 v4 = ((const float4*)(Vn + (size_t)kn * HH))[lane];
        float s = qv.x * k4.x + qv.y * k4.y + qv.z * k4.z + qv.w * k4.w;
        s += __shfl_xor_sync(0xffffffffu, s, 1);
        s += __shfl_xor_sync(0xffffffffu, s, 2);
        float ex = __expf(s * 0.25f);
        den += ex;
        acc.x += ex * v4.x;
        acc.y += ex * v4.y;
        acc.z += ex * v4.z;
        acc.w += ex * v4.w;
    }

    float inv = (end > beg) ? (1.f / den) : 0.f;
    float4 o = make_float4(acc.x * inv, acc.y * inv, acc.z * inv, acc.w * inv);
    ((float4*)(out + (size_t)i * HH))[lane] = o;
}

// ---------------- launch ----------------
extern "C" void kernel_launch(void* const* d_in, const int* in_sizes, int n_in,
                              void* d_out, int out_size) {
    const float* q = (const float*)d_in[0];
    const float* k = (const float*)d_in[1];
    const float* v = (const float*)d_in[2];
    const float* Wq = (const float*)d_in[3];
    const float* bq = (const float*)d_in[4];
    const float* Wk = (const float*)d_in[5];
    const float* bk = (const float*)d_in[6];
    const float* Wv = (const float*)d_in[7];
    const float* bv = (const float*)d_in[8];
    const int* qi = (const int*)d_in[9];
    const int* ki = (const int*)d_in[10];

    int Nn = in_sizes[0] / HH;   // 50000
    int E = in_sizes[9];         // 800000
    float* out = (float*)d_out;

    // weight transpose
    wt_kernel<<<dim3(64, 3), 256>>>(Wq, Wk, Wv);

    // CSR build over destination nodes (parallel 3-phase scan)
    int nb = (Nn + SCAN_BLK - 1) / SCAN_BLK;     // 49 for N=50000
    zero_kernel<<<(Nn + 255) / 256, 256>>>(Nn);
    hist_kernel<<<(E + 255) / 256, 256>>>(qi, E);
    scan1_kernel<<<nb, SCAN_BLK>>>(Nn);
    scan2_kernel<<<1, MAX_SCAN_BLOCKS>>>(nb, Nn);
    scan3_kernel<<<nb, SCAN_BLK>>>(Nn);
    scatter_kernel<<<(E + 255) / 256, 256>>>(qi, ki, E);

    // per-node projections Qn/Kn/Vn
    proj_gemm<<<dim3((Nn + BM - 1) / BM, 1, 3), 256>>>(q, k, v, bq, bk, bv, Nn);

    // fused gather + scores + softmax + aggregate
    attn_kernel<<<((long long)Nn * 32 + 255) / 256, 256>>>(out, Nn);
}

// round 9
// speedup vs baseline: 1.5728x; 1.0676x over previous
#include <cuda_runtime.h>

#define HH 128           // hidden dim
#define MAXN 50048
#define MAXE 800000
#define BM 128
#define BK 32
#define XS_STRIDE 132    // BM + 4 pad (16B-aligned row stride: 528B)
#define SCAN_BLK 1024
#define MAX_SCAN_BLOCKS 64

// ---------------- device scratch (no allocations allowed) ----------------
__device__ __align__(128) float g_P[3][(size_t)MAXN * HH];   // projected Qn,Kn,Vn
__device__ __align__(128) float g_WT[3][HH * HH];            // W transposed (k-major)
__device__ int g_count[MAXN];
__device__ int g_off[MAXN + 1];
__device__ int g_cursor[MAXN];
__device__ int g_kn[MAXE];        // CSR payload: source node id (ki[e]) directly
__device__ int g_bsum[MAX_SCAN_BLOCKS];
__device__ int g_bbase[MAX_SCAN_BLOCKS];

// ---------------- packed f32x2 helpers (Blackwell FFMA2) ----------------
__device__ __forceinline__ unsigned long long fma2(unsigned long long a,
                                                   unsigned long long b,
                                                   unsigned long long c) {
    unsigned long long d;
    asm("fma.rn.f32x2 %0, %1, %2, %3;" : "=l"(d) : "l"(a), "l"(b), "l"(c));
    return d;
}
__device__ __forceinline__ unsigned long long pack2(float lo, float hi) {
    unsigned long long d;
    asm("mov.b64 %0, {%1, %2};" : "=l"(d) : "f"(lo), "f"(hi));
    return d;
}
__device__ __forceinline__ float2 unpack2(unsigned long long v) {
    float2 r;
    asm("mov.b64 {%0, %1}, %2;" : "=f"(r.x), "=f"(r.y) : "l"(v));
    return r;
}

// ---------------- K0: transpose weights to k-major ----------------
__global__ void wt_kernel(const float* __restrict__ Wq,
                          const float* __restrict__ Wk,
                          const float* __restrict__ Wv) {
    int z = blockIdx.y;
    const float* W = (z == 0) ? Wq : (z == 1) ? Wk : Wv;
    int idx = blockIdx.x * 256 + threadIdx.x;
    if (idx < HH * HH) {
        int o = idx >> 7;
        int kk = idx & 127;
        g_WT[z][kk * HH + o] = W[idx];   // WT[k][o] = W[o][k]
    }
}

// ---------------- CSR build ----------------
__global__ void zero_kernel(int n) {
    int i = blockIdx.x * 256 + threadIdx.x;
    if (i < n) g_count[i] = 0;
}
__global__ void hist_kernel(const int* __restrict__ qi, int e) {
    int i = blockIdx.x * 256 + threadIdx.x;
    if (i < e) atomicAdd(&g_count[qi[i]], 1);
}
__global__ void __launch_bounds__(SCAN_BLK) scan1_kernel(int n) {
    __shared__ int wsum[32];
    int i = blockIdx.x * SCAN_BLK + threadIdx.x;
    int lane = threadIdx.x & 31;
    int wid = threadIdx.x >> 5;
    int v = (i < n) ? g_count[i] : 0;
    int x = v;
#pragma unroll
    for (int d = 1; d < 32; d <<= 1) {
        int y = __shfl_up_sync(0xffffffffu, x, d);
        if (lane >= d) x += y;
    }
    if (lane == 31) wsum[wid] = x;
    __syncthreads();
    if (wid == 0) {
        int s = wsum[lane];
#pragma unroll
        for (int d = 1; d < 32; d <<= 1) {
            int y = __shfl_up_sync(0xffffffffu, s, d);
            if (lane >= d) s += y;
        }
        wsum[lane] = s;
    }
    __syncthreads();
    int base = (wid > 0) ? wsum[wid - 1] : 0;
    int incl = base + x;
    if (i < n) g_off[i] = incl - v;
    if (threadIdx.x == SCAN_BLK - 1) g_bsum[blockIdx.x] = incl;
}
__global__ void scan2_kernel(int nb, int n) {
    __shared__ int s[MAX_SCAN_BLOCKS];
    int t = threadIdx.x;
    int v = (t < nb) ? g_bsum[t] : 0;
    s[t] = v;
    __syncthreads();
#pragma unroll
    for (int d = 1; d < MAX_SCAN_BLOCKS; d <<= 1) {
        int y = (t >= d) ? s[t - d] : 0;
        __syncthreads();
        s[t] += y;
        __syncthreads();
    }
    if (t < nb) g_bbase[t] = s[t] - v;
    if (t == nb - 1) g_off[n] = s[t];
}
__global__ void __launch_bounds__(SCAN_BLK) scan3_kernel(int n) {
    int i = blockIdx.x * SCAN_BLK + threadIdx.x;
    if (i < n) {
        int o = g_off[i] + g_bbase[blockIdx.x];
        g_off[i] = o;
        g_cursor[i] = o;
    }
}
// Scatter the SOURCE node id (not the edge id): attn needs only ki[e].
__global__ void scatter_kernel(const int* __restrict__ qi,
                               const int* __restrict__ ki, int e) {
    int i = blockIdx.x * 256 + threadIdx.x;
    if (i < e) {
        int pos = atomicAdd(&g_cursor[qi[i]], 1);
        g_kn[pos] = ki[i];
    }
}

// ---------------- K1: projection GEMM, Y = X @ W^T + b ----------------
// BM=128 rows x 128 cols per 256-thread block. Per thread: 16 rows x 4 cols,
// accumulated as 8x4 f32x2 (row pairs). W reads conflict-free, X broadcast.
__global__ void __launch_bounds__(256, 2) proj_gemm(
    const float* __restrict__ Xq, const float* __restrict__ Xk,
    const float* __restrict__ Xv,
    const float* __restrict__ Bq, const float* __restrict__ Bk,
    const float* __restrict__ Bv, int M) {
    __shared__ __align__(16) float Ws[BK * HH];         // Ws[k][o]
    __shared__ __align__(16) float Xs[BK * XS_STRIDE];  // Xs[k][row], padded

    int z = blockIdx.z;
    const float* X = (z == 0) ? Xq : (z == 1) ? Xk : Xv;
    const float* B = (z == 0) ? Bq : (z == 1) ? Bk : Bv;
    const float* WT = g_WT[z];
    float* Y = g_P[z];

    int t = threadIdx.x;
    int m0 = blockIdx.x * BM;
    int tx = t & 31;
    int ty = t >> 5;
    int c0 = tx * 4;    // 4 output cols
    int r0 = ty * 16;   // 16 output rows

    unsigned long long acc[8][4];
#pragma unroll
    for (int p = 0; p < 8; p++)
#pragma unroll
        for (int c = 0; c < 4; c++) acc[p][c] = 0ull;

    for (int kt = 0; kt < HH; kt += BK) {
        __syncthreads();
        // W tile: 4096 floats, straight float4 copy
        {
            const float4* src = (const float4*)(WT + kt * HH);
            float4* dst = (float4*)Ws;
#pragma unroll
            for (int i = 0; i < 4; i++) dst[t + i * 256] = src[t + i * 256];
        }
        // X tile: 128 rows x 32 cols, coalesced float4 loads, transposed scatter
        {
#pragma unroll
            for (int i = 0; i < 4; i++) {
                int idx = t + i * 256;      // 0..1023
                int row = idx >> 3;         // 0..127
                int c4 = idx & 7;           // float4 within 32 cols
                int gm = m0 + row;
                float4 xv = make_float4(0.f, 0.f, 0.f, 0.f);
                if (gm < M) xv = ((const float4*)X)[gm * (HH / 4) + (kt >> 2) + c4];
                int kk = c4 * 4;
                Xs[(kk + 0) * XS_STRIDE + row] = xv.x;
                Xs[(kk + 1) * XS_STRIDE + row] = xv.y;
                Xs[(kk + 2) * XS_STRIDE + row] = xv.z;
                Xs[(kk + 3) * XS_STRIDE + row] = xv.w;
            }
        }
        __syncthreads();

#pragma unroll 4
        for (int kk = 0; kk < BK; kk++) {
            float4 w4 = *(const float4*)(Ws + kk * HH + c0);
            unsigned long long b0 = pack2(w4.x, w4.x);
            unsigned long long b1 = pack2(w4.y, w4.y);
            unsigned long long b2 = pack2(w4.z, w4.z);
            unsigned long long b3 = pack2(w4.w, w4.w);
            const float* xp = Xs + kk * XS_STRIDE + r0;
            ulonglong2 aA = *(const ulonglong2*)(xp);        // rows r0..+3
            ulonglong2 aB = *(const ulonglong2*)(xp + 4);    // rows +4..+7
            ulonglong2 aC = *(const ulonglong2*)(xp + 8);    // rows +8..+11
            ulonglong2 aD = *(const ulonglong2*)(xp + 12);   // rows +12..+15
            unsigned long long a[8] = {aA.x, aA.y, aB.x, aB.y,
                                       aC.x, aC.y, aD.x, aD.y};
#pragma unroll
            for (int p = 0; p < 8; p++) {
                acc[p][0] = fma2(a[p], b0, acc[p][0]);
                acc[p][1] = fma2(a[p], b1, acc[p][1]);
                acc[p][2] = fma2(a[p], b2, acc[p][2]);
                acc[p][3] = fma2(a[p], b3, acc[p][3]);
            }
        }
    }

    float4 bias = *(const float4*)(B + c0);
#pragma unroll
    for (int p = 0; p < 8; p++) {
        float2 v0 = unpack2(acc[p][0]);
        float2 v1 = unpack2(acc[p][1]);
        float2 v2 = unpack2(acc[p][2]);
        float2 v3 = unpack2(acc[p][3]);
        int gm = m0 + r0 + 2 * p;
        if (gm < M) {
            float4 o0 = make_float4(v0.x + bias.x, v1.x + bias.y,
                                    v2.x + bias.z, v3.x + bias.w);
            *(float4*)(Y + (size_t)gm * HH + c0) = o0;
        }
        if (gm + 1 < M) {
            float4 o1 = make_float4(v0.y + bias.x, v1.y + bias.y,
                                    v2.y + bias.z, v3.y + bias.w);
            *(float4*)(Y + (size_t)(gm + 1) * HH + c0) = o1;
        }
    }
}

// ---------------- K3: warp-per-node attention (fused softmax) ----------------
// lane l owns dims [4l, 4l+4); head = l>>2 (D=16 => 4 lanes/head).
// ctx[i] = (sum_e ex_e * V_e) / (sum_e ex_e)  -- division deferred.
// Unrolled by 4: 8 independent 512B row loads in flight per iteration.
__global__ void __launch_bounds__(256) attn_kernel(float* __restrict__ out,
                                                   int n) {
    int warp = (blockIdx.x * blockDim.x + threadIdx.x) >> 5;
    int lane = threadIdx.x & 31;
    if (warp >= n) return;
    int i = warp;
    const float* Qn = g_P[0];
    const float* Kn = g_P[1];
    const float* Vn = g_P[2];

    float4 qv = ((const float4*)(Qn + (size_t)i * HH))[lane];
    int beg = g_off[i];
    int end = g_off[i + 1];

    float4 acc = make_float4(0.f, 0.f, 0.f, 0.f);
    float den = 0.f;

    int j = beg;
    for (; j + 3 < end; j += 4) {
        int kn0 = g_kn[j];
        int kn1 = g_kn[j + 1];
        int kn2 = g_kn[j + 2];
        int kn3 = g_kn[j + 3];
        float4 k0 = ((const float4*)(Kn + (size_t)kn0 * HH))[lane];
        float4 k1 = ((const float4*)(Kn + (size_t)kn1 * HH))[lane];
        float4 k2 = ((const float4*)(Kn + (size_t)kn2 * HH))[lane];
        float4 k3 = ((const float4*)(Kn + (size_t)kn3 * HH))[lane];
        float4 v0 = ((const float4*)(Vn + (size_t)kn0 * HH))[lane];
        float4 v1 = ((const float4*)(Vn + (size_t)kn1 * HH))[lane];
        float4 v2 = ((const float4*)(Vn + (size_t)kn2 * HH))[lane];
        float4 v3 = ((const float4*)(Vn + (size_t)kn3 * HH))[lane];
        float s0 = qv.x * k0.x + qv.y * k0.y + qv.z * k0.z + qv.w * k0.w;
        float s1 = qv.x * k1.x + qv.y * k1.y + qv.z * k1.z + qv.w * k1.w;
        float s2 = qv.x * k2.x + qv.y * k2.y + qv.z * k2.z + qv.w * k2.w;
        float s3 = qv.x * k3.x + qv.y * k3.y + qv.z * k3.z + qv.w * k3.w;
        s0 += __shfl_xor_sync(0xffffffffu, s0, 1);
        s1 += __shfl_xor_sync(0xffffffffu, s1, 1);
        s2 += __shfl_xor_sync(0xffffffffu, s2, 1);
        s3 += __shfl_xor_sync(0xffffffffu, s3, 1);
        s0 += __shfl_xor_sync(0xffffffffu, s0, 2);
        s1 += __shfl_xor_sync(0xffffffffu, s1, 2);
        s2 += __shfl_xor_sync(0xffffffffu, s2, 2);
        s3 += __shfl_xor_sync(0xffffffffu, s3, 2);
        float ex0 = __expf(s0 * 0.25f);
        float ex1 = __expf(s1 * 0.25f);
        float ex2 = __expf(s2 * 0.25f);
        float ex3 = __expf(s3 * 0.25f);
        den += (ex0 + ex1) + (ex2 + ex3);
        acc.x += ex0 * v0.x + ex1 * v1.x + ex2 * v2.x + ex3 * v3.x;
        acc.y += ex0 * v0.y + ex1 * v1.y + ex2 * v2.y + ex3 * v3.y;
        acc.z += ex0 * v0.z + ex1 * v1.z + ex2 * v2.z + ex3 * v3.z;
        acc.w += ex0 * v0.w + ex1 * v1.w + ex2 * v2.w + ex3 * v3.w;
    }
    for (; j < end; j++) {
        int kn = g_kn[j];
        float4 k4 = ((const float4*)(Kn + (size_t)kn * HH))[lane];
        float4 v4 = ((const float4*)(Vn + (size_t)kn * HH))[lane];
        float s = qv.x * k4.x + qv.y * k4.y + qv.z * k4.z + qv.w * k4.w;
        s += __shfl_xor_sync(0xffffffffu, s, 1);
        s += __shfl_xor_sync(0xffffffffu, s, 2);
        float ex = __expf(s * 0.25f);
        den += ex;
        acc.x += ex * v4.x;
        acc.y += ex * v4.y;
        acc.z += ex * v4.z;
        acc.w += ex * v4.w;
    }

    float inv = (end > beg) ? (1.f / den) : 0.f;
    float4 o = make_float4(acc.x * inv, acc.y * inv, acc.z * inv, acc.w * inv);
    ((float4*)(out + (size_t)i * HH))[lane] = o;
}

// ---------------- launch ----------------
extern "C" void kernel_launch(void* const* d_in, const int* in_sizes, int n_in,
                              void* d_out, int out_size) {
    const float* q = (const float*)d_in[0];
    const float* k = (const float*)d_in[1];
    const float* v = (const float*)d_in[2];
    const float* Wq = (const float*)d_in[3];
    const float* bq = (const float*)d_in[4];
    const float* Wk = (const float*)d_in[5];
    const float* bk = (const float*)d_in[6];
    const float* Wv = (const float*)d_in[7];
    const float* bv = (const float*)d_in[8];
    const int* qi = (const int*)d_in[9];
    const int* ki = (const int*)d_in[10];

    int Nn = in_sizes[0] / HH;   // 50000
    int E = in_sizes[9];         // 800000
    float* out = (float*)d_out;

    // One-time host-side resources (created outside graph capture on the
    // first, non-captured correctness call; no device memory involved).
    static cudaStream_t s2 = nullptr;
    static cudaEvent_t evFork = nullptr, evJoin = nullptr;
    if (s2 == nullptr) {
        cudaStreamCreateWithFlags(&s2, cudaStreamNonBlocking);
        cudaEventCreateWithFlags(&evFork, cudaEventDisableTiming);
        cudaEventCreateWithFlags(&evJoin, cudaEventDisableTiming);
    }

    // ---- fork: projection branch (wt + GEMM) runs concurrently with CSR ----
    cudaEventRecord(evFork, 0);
    cudaStreamWaitEvent(s2, evFork, 0);

    // Branch B (stream s2): weight transpose + per-node projections
    wt_kernel<<<dim3(64, 3), 256, 0, s2>>>(Wq, Wk, Wv);
    proj_gemm<<<dim3((Nn + BM - 1) / BM, 1, 3), 256, 0, s2>>>(
        q, k, v, bq, bk, bv, Nn);
    cudaEventRecord(evJoin, s2);

    // Branch A (origin stream): CSR build over destination nodes
    int nb = (Nn + SCAN_BLK - 1) / SCAN_BLK;     // 49 for N=50000
    zero_kernel<<<(Nn + 255) / 256, 256>>>(Nn);
    hist_kernel<<<(E + 255) / 256, 256>>>(qi, E);
    scan1_kernel<<<nb, SCAN_BLK>>>(Nn);
    scan2_kernel<<<1, MAX_SCAN_BLOCKS>>>(nb, Nn);
    scan3_kernel<<<nb, SCAN_BLK>>>(Nn);
    scatter_kernel<<<(E + 255) / 256, 256>>>(qi, ki, E);

    // ---- join: attention needs both branches ----
    cudaStreamWaitEvent(0, evJoin, 0);

    // fused gather + scores + softmax + aggregate
    attn_kernel<<<((long long)Nn * 32 + 255) / 256, 256>>>(out, Nn);
}

// round 12
// speedup vs baseline: 2.1402x; 1.3608x over previous
#include <cuda_runtime.h>
#include <cuda_bf16.h>
#include <cstdint>

#define HH 128           // hidden dim
#define MAXN 50048
#define MAXE 800000
#define SCAN_BLK 1024
#define MAX_SCAN_BLOCKS 64

// GEMM tiling
#define GBM 128          // CTA rows
#define GBK 64           // k tile
#define TSTRIDE_B 144    // padded row stride in bytes (72 bf16): conflict-free ldmatrix
#define SM_XH 0
#define SM_XL (128 * TSTRIDE_B)
#define SM_WH (2 * 128 * TSTRIDE_B)
#define SM_WL (3 * 128 * TSTRIDE_B)
#define SM_GEMM_TOTAL (4 * 128 * TSTRIDE_B)   // 73728 bytes

// ---------------- device scratch (no allocations allowed) ----------------
__device__ __align__(128) float g_P[3][(size_t)MAXN * HH];   // projected Qn,Kn,Vn
__device__ int g_count[MAXN];
__device__ int g_off[MAXN + 1];
__device__ int g_cursor[MAXN];
__device__ int g_kn[MAXE];        // CSR payload: source node id (ki[e]) directly
__device__ int g_bsum[MAX_SCAN_BLOCKS];
__device__ int g_bbase[MAX_SCAN_BLOCKS];

// ---------------- helpers ----------------
__device__ __forceinline__ uint32_t smem_u32(const void* p) {
    uint32_t a;
    asm("{ .reg .u64 t; cvta.to.shared.u64 t, %1; cvt.u32.u64 %0, t; }"
        : "=r"(a) : "l"(p));
    return a;
}
// Split float4 into hi/lo bf16 pairs packed as uint2 (2 bf16 per u32).
__device__ __forceinline__ void split4(float4 x, uint2& hi, uint2& lo) {
    __nv_bfloat16 h0 = __float2bfloat16(x.x);
    __nv_bfloat16 h1 = __float2bfloat16(x.y);
    __nv_bfloat16 h2 = __float2bfloat16(x.z);
    __nv_bfloat16 h3 = __float2bfloat16(x.w);
    __nv_bfloat16 l0 = __float2bfloat16(x.x - __bfloat162float(h0));
    __nv_bfloat16 l1 = __float2bfloat16(x.y - __bfloat162float(h1));
    __nv_bfloat16 l2 = __float2bfloat16(x.z - __bfloat162float(h2));
    __nv_bfloat16 l3 = __float2bfloat16(x.w - __bfloat162float(h3));
    hi.x = (uint32_t)__bfloat16_as_ushort(h0) | ((uint32_t)__bfloat16_as_ushort(h1) << 16);
    hi.y = (uint32_t)__bfloat16_as_ushort(h2) | ((uint32_t)__bfloat16_as_ushort(h3) << 16);
    lo.x = (uint32_t)__bfloat16_as_ushort(l0) | ((uint32_t)__bfloat16_as_ushort(l1) << 16);
    lo.y = (uint32_t)__bfloat16_as_ushort(l2) | ((uint32_t)__bfloat16_as_ushort(l3) << 16);
}
__device__ __forceinline__ void ldmA(uint32_t addr, uint32_t* a) {
    asm volatile("ldmatrix.sync.aligned.m8n8.x4.shared.b16 {%0,%1,%2,%3}, [%4];"
                 : "=r"(a[0]), "=r"(a[1]), "=r"(a[2]), "=r"(a[3]) : "r"(addr));
}
__device__ __forceinline__ void ldmB(uint32_t addr, uint32_t* b) {
    asm volatile("ldmatrix.sync.aligned.m8n8.x2.shared.b16 {%0,%1}, [%2];"
                 : "=r"(b[0]), "=r"(b[1]) : "r"(addr));
}
__device__ __forceinline__ void mma_bf16(float* c, const uint32_t* a, const uint32_t* b) {
    asm volatile(
        "mma.sync.aligned.m16n8k16.row.col.f32.bf16.bf16.f32 "
        "{%0,%1,%2,%3}, {%4,%5,%6,%7}, {%8,%9}, {%0,%1,%2,%3};"
        : "+f"(c[0]), "+f"(c[1]), "+f"(c[2]), "+f"(c[3])
        : "r"(a[0]), "r"(a[1]), "r"(a[2]), "r"(a[3]), "r"(b[0]), "r"(b[1]));
}

// ---------------- CSR build ----------------
__global__ void zero_kernel(int n) {
    int i = blockIdx.x * 256 + threadIdx.x;
    if (i < n) g_count[i] = 0;
}
__global__ void hist_kernel(const int* __restrict__ qi, int e) {
    int i = blockIdx.x * 256 + threadIdx.x;
    if (i < e) atomicAdd(&g_count[qi[i]], 1);
}
__global__ void __launch_bounds__(SCAN_BLK) scan1_kernel(int n) {
    __shared__ int wsum[32];
    int i = blockIdx.x * SCAN_BLK + threadIdx.x;
    int lane = threadIdx.x & 31;
    int wid = threadIdx.x >> 5;
    int v = (i < n) ? g_count[i] : 0;
    int x = v;
#pragma unroll
    for (int d = 1; d < 32; d <<= 1) {
        int y = __shfl_up_sync(0xffffffffu, x, d);
        if (lane >= d) x += y;
    }
    if (lane == 31) wsum[wid] = x;
    __syncthreads();
    if (wid == 0) {
        int s = wsum[lane];
#pragma unroll
        for (int d = 1; d < 32; d <<= 1) {
            int y = __shfl_up_sync(0xffffffffu, s, d);
            if (lane >= d) s += y;
        }
        wsum[lane] = s;
    }
    __syncthreads();
    int base = (wid > 0) ? wsum[wid - 1] : 0;
    int incl = base + x;
    if (i < n) g_off[i] = incl - v;
    if (threadIdx.x == SCAN_BLK - 1) g_bsum[blockIdx.x] = incl;
}
__global__ void scan2_kernel(int nb, int n) {
    __shared__ int s[MAX_SCAN_BLOCKS];
    int t = threadIdx.x;
    int v = (t < nb) ? g_bsum[t] : 0;
    s[t] = v;
    __syncthreads();
#pragma unroll
    for (int d = 1; d < MAX_SCAN_BLOCKS; d <<= 1) {
        int y = (t >= d) ? s[t - d] : 0;
        __syncthreads();
        s[t] += y;
        __syncthreads();
    }
    if (t < nb) g_bbase[t] = s[t] - v;
    if (t == nb - 1) g_off[n] = s[t];
}
__global__ void __launch_bounds__(SCAN_BLK) scan3_kernel(int n) {
    int i = blockIdx.x * SCAN_BLK + threadIdx.x;
    if (i < n) {
        int o = g_off[i] + g_bbase[blockIdx.x];
        g_off[i] = o;
        g_cursor[i] = o;
    }
}
__global__ void scatter_kernel(const int* __restrict__ qi,
                               const int* __restrict__ ki, int e) {
    int i = blockIdx.x * 256 + threadIdx.x;
    if (i < e) {
        int pos = atomicAdd(&g_cursor[qi[i]], 1);
        g_kn[pos] = ki[i];
    }
}

// ---------------- K1: split-bf16 HMMA projection GEMM ----------------
// Y = X @ W^T + b via mma.sync m16n8k16 bf16, 3-pass error compensation:
// X = Xh + Xl, W = Wh + Wl;  Y ~= Xh*Wh + Xh*Wl + Xl*Wh  (fp32 accum).
// CTA: 128 rows x 128 cols, 8 warps each own a 16-col slab. BK=64, 2 k-tiles.
__global__ void __launch_bounds__(256) proj_mma(
    const float* __restrict__ Xq, const float* __restrict__ Xk,
    const float* __restrict__ Xv,
    const float* __restrict__ Wq, const float* __restrict__ Wk,
    const float* __restrict__ Wv,
    const float* __restrict__ Bq, const float* __restrict__ Bk,
    const float* __restrict__ Bv, int M) {
    extern __shared__ char smem[];
    uint32_t sb = smem_u32(smem);

    int z = blockIdx.z;
    const float* X = (z == 0) ? Xq : (z == 1) ? Xk : Xv;
    const float* W = (z == 0) ? Wq : (z == 1) ? Wk : Wv;
    const float* B = (z == 0) ? Bq : (z == 1) ? Bk : Bv;
    float* Y = g_P[z];

    int t = threadIdx.x;
    int warp = t >> 5;
    int lane = t & 31;
    int m0 = blockIdx.x * GBM;
    int wbase = warp * 16;            // output column base of this warp
    int gid = lane >> 2;              // group id (0..7)
    int tig = lane & 3;               // thread in group

    // Lane-constant ldmatrix base offsets.
    // A: lane l -> matrix m = l>>3, row (m&1)*8 + (l&7), k-half (m>>1)*8
    int am = lane >> 3;
    uint32_t aRow = (uint32_t)(((am & 1) << 3) + (lane & 7));
    uint32_t aK = (uint32_t)((am >> 1) << 3);
    uint32_t aBaseH = sb + SM_XH + aRow * TSTRIDE_B + aK * 2;
    uint32_t aBaseL = sb + SM_XL + aRow * TSTRIDE_B + aK * 2;
    // B: lanes 0-15 meaningful: n = wbase + (li&7), k-half = (li>>3)*8
    int li = lane & 15;
    uint32_t bRow = (uint32_t)(wbase + (li & 7));
    uint32_t bK = (uint32_t)((li >> 3) << 3);
    uint32_t bBaseH = sb + SM_WH + bRow * TSTRIDE_B + bK * 2;
    uint32_t bBaseL = sb + SM_WL + bRow * TSTRIDE_B + bK * 2;

    float acc[8][2][4];
#pragma unroll
    for (int mt = 0; mt < 8; mt++)
#pragma unroll
        for (int nt = 0; nt < 2; nt++)
#pragma unroll
            for (int c = 0; c < 4; c++) acc[mt][nt][c] = 0.f;

    for (int kt = 0; kt < HH; kt += GBK) {
        __syncthreads();
        // Fill X tile (128 x 64 fp32 -> hi/lo bf16) — coalesced float4 loads.
#pragma unroll
        for (int i = 0; i < 8; i++) {
            int idx = t + i * 256;        // 0..2047
            int row = idx >> 4;           // 0..127
            int c4 = idx & 15;            // float4 within 64 cols
            int gm = m0 + row;
            float4 xv = make_float4(0.f, 0.f, 0.f, 0.f);
            if (gm < M) xv = ((const float4*)X)[gm * (HH / 4) + (kt >> 2) + c4];
            uint2 hi, lo;
            split4(xv, hi, lo);
            uint32_t off = (uint32_t)row * TSTRIDE_B + (uint32_t)c4 * 8;
            *(uint2*)(smem + SM_XH + off) = hi;
            *(uint2*)(smem + SM_XL + off) = lo;
        }
        // Fill W tile (128 x 64)
#pragma unroll
        for (int i = 0; i < 8; i++) {
            int idx = t + i * 256;
            int row = idx >> 4;
            int c4 = idx & 15;
            float4 wv = ((const float4*)W)[row * (HH / 4) + (kt >> 2) + c4];
            uint2 hi, lo;
            split4(wv, hi, lo);
            uint32_t off = (uint32_t)row * TSTRIDE_B + (uint32_t)c4 * 8;
            *(uint2*)(smem + SM_WH + off) = hi;
            *(uint2*)(smem + SM_WL + off) = lo;
        }
        __syncthreads();

#pragma unroll
        for (int ks = 0; ks < 4; ks++) {
            uint32_t ksOff = (uint32_t)ks * 32;   // 16 bf16 = 32 bytes
            uint32_t bh[2][2], bl[2][2];
#pragma unroll
            for (int nt = 0; nt < 2; nt++) {
                uint32_t ntOff = (uint32_t)nt * 8 * TSTRIDE_B;
                ldmB(bBaseH + ntOff + ksOff, bh[nt]);
                ldmB(bBaseL + ntOff + ksOff, bl[nt]);
            }
#pragma unroll
            for (int mt = 0; mt < 8; mt++) {
                uint32_t mtOff = (uint32_t)mt * 16 * TSTRIDE_B;
                uint32_t ah[4], al[4];
                ldmA(aBaseH + mtOff + ksOff, ah);
                ldmA(aBaseL + mtOff + ksOff, al);
#pragma unroll
                for (int nt = 0; nt < 2; nt++) {
                    mma_bf16(acc[mt][nt], ah, bh[nt]);
                    mma_bf16(acc[mt][nt], ah, bl[nt]);
                    mma_bf16(acc[mt][nt], al, bh[nt]);
                }
            }
        }
    }

    // Epilogue: acc[mt][nt] tile maps rows m0+mt*16+gid(+8), cols wbase+nt*8+2tig.
#pragma unroll
    for (int nt = 0; nt < 2; nt++) {
        int col = wbase + nt * 8 + tig * 2;
        float2 bias = *(const float2*)(B + col);
#pragma unroll
        for (int mt = 0; mt < 8; mt++) {
            int r0 = m0 + mt * 16 + gid;
            if (r0 < M) {
                float2 o = make_float2(acc[mt][nt][0] + bias.x,
                                       acc[mt][nt][1] + bias.y);
                *(float2*)(Y + (size_t)r0 * HH + col) = o;
            }
            int r1 = r0 + 8;
            if (r1 < M) {
                float2 o = make_float2(acc[mt][nt][2] + bias.x,
                                       acc[mt][nt][3] + bias.y);
                *(float2*)(Y + (size_t)r1 * HH + col) = o;
            }
        }
    }
}

// ---------------- K3: warp-per-node attention (fused softmax) ----------------
__global__ void __launch_bounds__(256) attn_kernel(float* __restrict__ out,
                                                   int n) {
    int warp = (blockIdx.x * blockDim.x + threadIdx.x) >> 5;
    int lane = threadIdx.x & 31;
    if (warp >= n) return;
    int i = warp;
    const float* Qn = g_P[0];
    const float* Kn = g_P[1];
    const float* Vn = g_P[2];

    float4 qv = ((const float4*)(Qn + (size_t)i * HH))[lane];
    int beg = g_off[i];
    int end = g_off[i + 1];

    float4 acc = make_float4(0.f, 0.f, 0.f, 0.f);
    float den = 0.f;

    int j = beg;
    for (; j + 3 < end; j += 4) {
        int kn0 = g_kn[j];
        int kn1 = g_kn[j + 1];
        int kn2 = g_kn[j + 2];
        int kn3 = g_kn[j + 3];
        float4 k0 = ((const float4*)(Kn + (size_t)kn0 * HH))[lane];
        float4 k1 = ((const float4*)(Kn + (size_t)kn1 * HH))[lane];
        float4 k2 = ((const float4*)(Kn + (size_t)kn2 * HH))[lane];
        float4 k3 = ((const float4*)(Kn + (size_t)kn3 * HH))[lane];
        float4 v0 = ((const float4*)(Vn + (size_t)kn0 * HH))[lane];
        float4 v1 = ((const float4*)(Vn + (size_t)kn1 * HH))[lane];
        float4 v2 = ((const float4*)(Vn + (size_t)kn2 * HH))[lane];
        float4 v3 = ((const float4*)(Vn + (size_t)kn3 * HH))[lane];
        float s0 = qv.x * k0.x + qv.y * k0.y + qv.z * k0.z + qv.w * k0.w;
        float s1 = qv.x * k1.x + qv.y * k1.y + qv.z * k1.z + qv.w * k1.w;
        float s2 = qv.x * k2.x + qv.y * k2.y + qv.z * k2.z + qv.w * k2.w;
        float s3 = qv.x * k3.x + qv.y * k3.y + qv.z * k3.z + qv.w * k3.w;
        s0 += __shfl_xor_sync(0xffffffffu, s0, 1);
        s1 += __shfl_xor_sync(0xffffffffu, s1, 1);
        s2 += __shfl_xor_sync(0xffffffffu, s2, 1);
        s3 += __shfl_xor_sync(0xffffffffu, s3, 1);
        s0 += __shfl_xor_sync(0xffffffffu, s0, 2);
        s1 += __shfl_xor_sync(0xffffffffu, s1, 2);
        s2 += __shfl_xor_sync(0xffffffffu, s2, 2);
        s3 += __shfl_xor_sync(0xffffffffu, s3, 2);
        float ex0 = __expf(s0 * 0.25f);
        float ex1 = __expf(s1 * 0.25f);
        float ex2 = __expf(s2 * 0.25f);
        float ex3 = __expf(s3 * 0.25f);
        den += (ex0 + ex1) + (ex2 + ex3);
        acc.x += ex0 * v0.x + ex1 * v1.x + ex2 * v2.x + ex3 * v3.x;
        acc.y += ex0 * v0.y + ex1 * v1.y + ex2 * v2.y + ex3 * v3.y;
        acc.z += ex0 * v0.z + ex1 * v1.z + ex2 * v2.z + ex3 * v3.z;
        acc.w += ex0 * v0.w + ex1 * v1.w + ex2 * v2.w + ex3 * v3.w;
    }
    for (; j < end; j++) {
        int kn = g_kn[j];
        float4 k4 = ((const float4*)(Kn + (size_t)kn * HH))[lane];
        float4 v4 = ((const float4*)(Vn + (size_t)kn * HH))[lane];
        float s = qv.x * k4.x + qv.y * k4.y + qv.z * k4.z + qv.w * k4.w;
        s += __shfl_xor_sync(0xffffffffu, s, 1);
        s += __shfl_xor_sync(0xffffffffu, s, 2);
        float ex = __expf(s * 0.25f);
        den += ex;
        acc.x += ex * v4.x;
        acc.y += ex * v4.y;
        acc.z += ex * v4.z;
        acc.w += ex * v4.w;
    }

    float inv = (end > beg) ? (1.f / den) : 0.f;
    float4 o = make_float4(acc.x * inv, acc.y * inv, acc.z * inv, acc.w * inv);
    ((float4*)(out + (size_t)i * HH))[lane] = o;
}

// ---------------- launch ----------------
extern "C" void kernel_launch(void* const* d_in, const int* in_sizes, int n_in,
                              void* d_out, int out_size) {
    const float* q = (const float*)d_in[0];
    const float* k = (const float*)d_in[1];
    const float* v = (const float*)d_in[2];
    const float* Wq = (const float*)d_in[3];
    const float* bq = (const float*)d_in[4];
    const float* Wk = (const float*)d_in[5];
    const float* bk = (const float*)d_in[6];
    const float* Wv = (const float*)d_in[7];
    const float* bv = (const float*)d_in[8];
    const int* qi = (const int*)d_in[9];
    const int* ki = (const int*)d_in[10];

    int Nn = in_sizes[0] / HH;   // 50000
    int E = in_sizes[9];         // 800000
    float* out = (float*)d_out;

    // One-time host-side resources (no device memory involved).
    static cudaStream_t s2 = nullptr;
    static cudaEvent_t evFork = nullptr, evJoin = nullptr;
    if (s2 == nullptr) {
        cudaStreamCreateWithFlags(&s2, cudaStreamNonBlocking);
        cudaEventCreateWithFlags(&evFork, cudaEventDisableTiming);
        cudaEventCreateWithFlags(&evJoin, cudaEventDisableTiming);
        cudaFuncSetAttribute(proj_mma,
                             cudaFuncAttributeMaxDynamicSharedMemorySize,
                             SM_GEMM_TOTAL);
    }

    // ---- fork: projection branch runs concurrently with CSR build ----
    cudaEventRecord(evFork, 0);
    cudaStreamWaitEvent(s2, evFork, 0);

    // Branch B (stream s2): per-node projections on HMMA (split-bf16)
    proj_mma<<<dim3((Nn + GBM - 1) / GBM, 1, 3), 256, SM_GEMM_TOTAL, s2>>>(
        q, k, v, Wq, Wk, Wv, bq, bk, bv, Nn);
    cudaEventRecord(evJoin, s2);

    // Branch A (origin stream): CSR build over destination nodes
    int nb = (Nn + SCAN_BLK - 1) / SCAN_BLK;     // 49 for N=50000
    zero_kernel<<<(Nn + 255) / 256, 256>>>(Nn);
    hist_kernel<<<(E + 255) / 256, 256>>>(qi, E);
    scan1_kernel<<<nb, SCAN_BLK>>>(Nn);
    scan2_kernel<<<1, MAX_SCAN_BLOCKS>>>(nb, Nn);
    scan3_kernel<<<nb, SCAN_BLK>>>(Nn);
    scatter_kernel<<<(E + 255) / 256, 256>>>(qi, ki, E);

    // ---- join: attention needs both branches ----
    cudaStreamWaitEvent(0, evJoin, 0);

    // fused gather + scores + softmax + aggregate
    attn_kernel<<<((long long)Nn * 32 + 255) / 256, 256>>>(out, Nn);
}

// round 17
// speedup vs baseline: 2.2400x; 1.0466x over previous
#include <cuda_runtime.h>
#include <cuda_bf16.h>
#include <cuda_fp16.h>
#include <cstdint>

#define HH 128           // hidden dim
#define MAXN 50048
#define MAXE 800000
#define SCAN_BLK 1024
#define MAX_SCAN_BLOCKS 64

// GEMM tiling
#define GBM 128          // CTA rows
#define GBK 64           // k tile
#define TSTRIDE_B 144    // padded row stride in bytes (72 bf16): conflict-free ldmatrix
#define SM_XH 0
#define SM_XL (128 * TSTRIDE_B)
#define SM_WH (2 * 128 * TSTRIDE_B)
#define SM_WL (3 * 128 * TSTRIDE_B)
#define SM_GEMM_TOTAL (4 * 128 * TSTRIDE_B)   // 73728 bytes

// ---------------- device scratch (no allocations allowed) ----------------
__device__ __align__(128) float  g_Q[(size_t)MAXN * HH];     // projected Q (fp32)
__device__ __align__(128) __half g_Kh[(size_t)MAXN * HH];    // projected K (fp16)
__device__ __align__(128) __half g_Vh[(size_t)MAXN * HH];    // projected V (fp16)
__device__ int g_count[MAXN];
__device__ int g_off[MAXN + 1];
__device__ int g_cursor[MAXN];
__device__ int g_kn[MAXE];        // CSR payload: source node id (ki[e]) directly
__device__ int g_bsum[MAX_SCAN_BLOCKS];
__device__ int g_bbase[MAX_SCAN_BLOCKS];

// ---------------- helpers ----------------
__device__ __forceinline__ uint32_t smem_u32(const void* p) {
    uint32_t a;
    asm("{ .reg .u64 t; cvta.to.shared.u64 t, %1; cvt.u32.u64 %0, t; }"
        : "=r"(a) : "l"(p));
    return a;
}
// Split float4 into hi/lo bf16 pairs packed as uint2 (2 bf16 per u32).
__device__ __forceinline__ void split4(float4 x, uint2& hi, uint2& lo) {
    __nv_bfloat16 h0 = __float2bfloat16(x.x);
    __nv_bfloat16 h1 = __float2bfloat16(x.y);
    __nv_bfloat16 h2 = __float2bfloat16(x.z);
    __nv_bfloat16 h3 = __float2bfloat16(x.w);
    __nv_bfloat16 l0 = __float2bfloat16(x.x - __bfloat162float(h0));
    __nv_bfloat16 l1 = __float2bfloat16(x.y - __bfloat162float(h1));
    __nv_bfloat16 l2 = __float2bfloat16(x.z - __bfloat162float(h2));
    __nv_bfloat16 l3 = __float2bfloat16(x.w - __bfloat162float(h3));
    hi.x = (uint32_t)__bfloat16_as_ushort(h0) | ((uint32_t)__bfloat16_as_ushort(h1) << 16);
    hi.y = (uint32_t)__bfloat16_as_ushort(h2) | ((uint32_t)__bfloat16_as_ushort(h3) << 16);
    lo.x = (uint32_t)__bfloat16_as_ushort(l0) | ((uint32_t)__bfloat16_as_ushort(l1) << 16);
    lo.y = (uint32_t)__bfloat16_as_ushort(l2) | ((uint32_t)__bfloat16_as_ushort(l3) << 16);
}
__device__ __forceinline__ void ldmA(uint32_t addr, uint32_t* a) {
    asm volatile("ldmatrix.sync.aligned.m8n8.x4.shared.b16 {%0,%1,%2,%3}, [%4];"
                 : "=r"(a[0]), "=r"(a[1]), "=r"(a[2]), "=r"(a[3]) : "r"(addr));
}
__device__ __forceinline__ void ldmB(uint32_t addr, uint32_t* b) {
    asm volatile("ldmatrix.sync.aligned.m8n8.x2.shared.b16 {%0,%1}, [%2];"
                 : "=r"(b[0]), "=r"(b[1]) : "r"(addr));
}
__device__ __forceinline__ void mma_bf16(float* c, const uint32_t* a, const uint32_t* b) {
    asm volatile(
        "mma.sync.aligned.m16n8k16.row.col.f32.bf16.bf16.f32 "
        "{%0,%1,%2,%3}, {%4,%5,%6,%7}, {%8,%9}, {%0,%1,%2,%3};"
        : "+f"(c[0]), "+f"(c[1]), "+f"(c[2]), "+f"(c[3])
        : "r"(a[0]), "r"(a[1]), "r"(a[2]), "r"(a[3]), "r"(b[0]), "r"(b[1]));
}

// ---------------- CSR build ----------------
__global__ void zero_kernel(int n) {
    int i = blockIdx.x * 256 + threadIdx.x;
    if (i < n) g_count[i] = 0;
}
__global__ void hist_kernel(const int* __restrict__ qi, int e) {
    int i = blockIdx.x * 256 + threadIdx.x;
    if (i < e) atomicAdd(&g_count[qi[i]], 1);
}
__global__ void __launch_bounds__(SCAN_BLK) scan1_kernel(int n) {
    __shared__ int wsum[32];
    int i = blockIdx.x * SCAN_BLK + threadIdx.x;
    int lane = threadIdx.x & 31;
    int wid = threadIdx.x >> 5;
    int v = (i < n) ? g_count[i] : 0;
    int x = v;
#pragma unroll
    for (int d = 1; d < 32; d <<= 1) {
        int y = __shfl_up_sync(0xffffffffu, x, d);
        if (lane >= d) x += y;
    }
    if (lane == 31) wsum[wid] = x;
    __syncthreads();
    if (wid == 0) {
        int s = wsum[lane];
#pragma unroll
        for (int d = 1; d < 32; d <<= 1) {
            int y = __shfl_up_sync(0xffffffffu, s, d);
            if (lane >= d) s += y;
        }
        wsum[lane] = s;
    }
    __syncthreads();
    int base = (wid > 0) ? wsum[wid - 1] : 0;
    int incl = base + x;
    if (i < n) g_off[i] = incl - v;
    if (threadIdx.x == SCAN_BLK - 1) g_bsum[blockIdx.x] = incl;
}
__global__ void scan2_kernel(int nb, int n) {
    __shared__ int s[MAX_SCAN_BLOCKS];
    int t = threadIdx.x;
    int v = (t < nb) ? g_bsum[t] : 0;
    s[t] = v;
    __syncthreads();
#pragma unroll
    for (int d = 1; d < MAX_SCAN_BLOCKS; d <<= 1) {
        int y = (t >= d) ? s[t - d] : 0;
        __syncthreads();
        s[t] += y;
        __syncthreads();
    }
    if (t < nb) g_bbase[t] = s[t] - v;
    if (t == nb - 1) g_off[n] = s[t];
}
__global__ void __launch_bounds__(SCAN_BLK) scan3_kernel(int n) {
    int i = blockIdx.x * SCAN_BLK + threadIdx.x;
    if (i < n) {
        int o = g_off[i] + g_bbase[blockIdx.x];
        g_off[i] = o;
        g_cursor[i] = o;
    }
}
__global__ void scatter_kernel(const int* __restrict__ qi,
                               const int* __restrict__ ki, int e) {
    int i = blockIdx.x * 256 + threadIdx.x;
    if (i < e) {
        int pos = atomicAdd(&g_cursor[qi[i]], 1);
        g_kn[pos] = ki[i];
    }
}

// ---------------- K1: split-bf16 HMMA projection GEMM ----------------
// Y = X @ W^T + b via mma.sync m16n8k16 bf16, 3-pass error compensation.
// z=0 -> Q stored fp32; z=1/2 -> K/V stored fp16 (halves attention traffic).
__global__ void __launch_bounds__(256) proj_mma(
    const float* __restrict__ Xq, const float* __restrict__ Xk,
    const float* __restrict__ Xv,
    const float* __restrict__ Wq, const float* __restrict__ Wk,
    const float* __restrict__ Wv,
    const float* __restrict__ Bq, const float* __restrict__ Bk,
    const float* __restrict__ Bv, int M) {
    extern __shared__ char smem[];
    uint32_t sb = smem_u32(smem);

    int z = blockIdx.z;
    const float* X = (z == 0) ? Xq : (z == 1) ? Xk : Xv;
    const float* W = (z == 0) ? Wq : (z == 1) ? Wk : Wv;
    const float* B = (z == 0) ? Bq : (z == 1) ? Bk : Bv;

    int t = threadIdx.x;
    int warp = t >> 5;
    int lane = t & 31;
    int m0 = blockIdx.x * GBM;
    int wbase = warp * 16;            // output column base of this warp
    int gid = lane >> 2;              // group id (0..7)
    int tig = lane & 3;               // thread in group

    int am = lane >> 3;
    uint32_t aRow = (uint32_t)(((am & 1) << 3) + (lane & 7));
    uint32_t aK = (uint32_t)((am >> 1) << 3);
    uint32_t aBaseH = sb + SM_XH + aRow * TSTRIDE_B + aK * 2;
    uint32_t aBaseL = sb + SM_XL + aRow * TSTRIDE_B + aK * 2;
    int li = lane & 15;
    uint32_t bRow = (uint32_t)(wbase + (li & 7));
    uint32_t bK = (uint32_t)((li >> 3) << 3);
    uint32_t bBaseH = sb + SM_WH + bRow * TSTRIDE_B + bK * 2;
    uint32_t bBaseL = sb + SM_WL + bRow * TSTRIDE_B + bK * 2;

    float acc[8][2][4];
#pragma unroll
    for (int mt = 0; mt < 8; mt++)
#pragma unroll
        for (int nt = 0; nt < 2; nt++)
#pragma unroll
            for (int c = 0; c < 4; c++) acc[mt][nt][c] = 0.f;

    for (int kt = 0; kt < HH; kt += GBK) {
        __syncthreads();
#pragma unroll
        for (int i = 0; i < 8; i++) {
            int idx = t + i * 256;        // 0..2047
            int row = idx >> 4;           // 0..127
            int c4 = idx & 15;            // float4 within 64 cols
            int gm = m0 + row;
            float4 xv = make_float4(0.f, 0.f, 0.f, 0.f);
            if (gm < M) xv = ((const float4*)X)[gm * (HH / 4) + (kt >> 2) + c4];
            uint2 hi, lo;
            split4(xv, hi, lo);
            uint32_t off = (uint32_t)row * TSTRIDE_B + (uint32_t)c4 * 8;
            *(uint2*)(smem + SM_XH + off) = hi;
            *(uint2*)(smem + SM_XL + off) = lo;
        }
#pragma unroll
        for (int i = 0; i < 8; i++) {
            int idx = t + i * 256;
            int row = idx >> 4;
            int c4 = idx & 15;
            float4 wv = ((const float4*)W)[row * (HH / 4) + (kt >> 2) + c4];
            uint2 hi, lo;
            split4(wv, hi, lo);
            uint32_t off = (uint32_t)row * TSTRIDE_B + (uint32_t)c4 * 8;
            *(uint2*)(smem + SM_WH + off) = hi;
            *(uint2*)(smem + SM_WL + off) = lo;
        }
        __syncthreads();

#pragma unroll
        for (int ks = 0; ks < 4; ks++) {
            uint32_t ksOff = (uint32_t)ks * 32;   // 16 bf16 = 32 bytes
            uint32_t bh[2][2], bl[2][2];
#pragma unroll
            for (int nt = 0; nt < 2; nt++) {
                uint32_t ntOff = (uint32_t)nt * 8 * TSTRIDE_B;
                ldmB(bBaseH + ntOff + ksOff, bh[nt]);
                ldmB(bBaseL + ntOff + ksOff, bl[nt]);
            }
#pragma unroll
            for (int mt = 0; mt < 8; mt++) {
                uint32_t mtOff = (uint32_t)mt * 16 * TSTRIDE_B;
                uint32_t ah[4], al[4];
                ldmA(aBaseH + mtOff + ksOff, ah);
                ldmA(aBaseL + mtOff + ksOff, al);
#pragma unroll
                for (int nt = 0; nt < 2; nt++) {
                    mma_bf16(acc[mt][nt], ah, bh[nt]);
                    mma_bf16(acc[mt][nt], ah, bl[nt]);
                    mma_bf16(acc[mt][nt], al, bh[nt]);
                }
            }
        }
    }

    // Epilogue: rows m0+mt*16+gid(+8), cols wbase+nt*8+2tig.
    __half* Yh = (z == 1) ? g_Kh : g_Vh;
#pragma unroll
    for (int nt = 0; nt < 2; nt++) {
        int col = wbase + nt * 8 + tig * 2;
        float2 bias = *(const float2*)(B + col);
#pragma unroll
        for (int mt = 0; mt < 8; mt++) {
            int r0 = m0 + mt * 16 + gid;
            int r1 = r0 + 8;
            float2 o0 = make_float2(acc[mt][nt][0] + bias.x,
                                    acc[mt][nt][1] + bias.y);
            float2 o1 = make_float2(acc[mt][nt][2] + bias.x,
                                    acc[mt][nt][3] + bias.y);
            if (z == 0) {
                if (r0 < M) *(float2*)(g_Q + (size_t)r0 * HH + col) = o0;
                if (r1 < M) *(float2*)(g_Q + (size_t)r1 * HH + col) = o1;
            } else {
                if (r0 < M) *(__half2*)(Yh + (size_t)r0 * HH + col) = __float22half2_rn(o0);
                if (r1 < M) *(__half2*)(Yh + (size_t)r1 * HH + col) = __float22half2_rn(o1);
            }
        }
    }
}

// ---------------- K3: warp-per-node attention (fused softmax) ----------------
// lane l owns dims [4l, 4l+4); head = l>>2 (D=16 => 4 lanes/head).
// K/V rows are fp16 (256 B/row); Q fp32. Unrolled by 4 (8 rows in flight).
__device__ __forceinline__ float4 ld_half4(const __half* p) {
    uint2 u = *(const uint2*)p;
    float2 a = __half22float2(*(const __half2*)&u.x);
    float2 b = __half22float2(*(const __half2*)&u.y);
    return make_float4(a.x, a.y, b.x, b.y);
}
__global__ void __launch_bounds__(256) attn_kernel(float* __restrict__ out,
                                                   int n) {
    int warp = (blockIdx.x * blockDim.x + threadIdx.x) >> 5;
    int lane = threadIdx.x & 31;
    if (warp >= n) return;
    int i = warp;

    float4 qv = ((const float4*)(g_Q + (size_t)i * HH))[lane];
    int beg = g_off[i];
    int end = g_off[i + 1];

    float4 acc = make_float4(0.f, 0.f, 0.f, 0.f);
    float den = 0.f;

    int j = beg;
    for (; j + 3 < end; j += 4) {
        int kn0 = g_kn[j];
        int kn1 = g_kn[j + 1];
        int kn2 = g_kn[j + 2];
        int kn3 = g_kn[j + 3];
        float4 k0 = ld_half4(g_Kh + (size_t)kn0 * HH + lane * 4);
        float4 k1 = ld_half4(g_Kh + (size_t)kn1 * HH + lane * 4);
        float4 k2 = ld_half4(g_Kh + (size_t)kn2 * HH + lane * 4);
        float4 k3 = ld_half4(g_Kh + (size_t)kn3 * HH + lane * 4);
        float4 v0 = ld_half4(g_Vh + (size_t)kn0 * HH + lane * 4);
        float4 v1 = ld_half4(g_Vh + (size_t)kn1 * HH + lane * 4);
        float4 v2 = ld_half4(g_Vh + (size_t)kn2 * HH + lane * 4);
        float4 v3 = ld_half4(g_Vh + (size_t)kn3 * HH + lane * 4);
        float s0 = qv.x * k0.x + qv.y * k0.y + qv.z * k0.z + qv.w * k0.w;
        float s1 = qv.x * k1.x + qv.y * k1.y + qv.z * k1.z + qv.w * k1.w;
        float s2 = qv.x * k2.x + qv.y * k2.y + qv.z * k2.z + qv.w * k2.w;
        float s3 = qv.x * k3.x + qv.y * k3.y + qv.z * k3.z + qv.w * k3.w;
        s0 += __shfl_xor_sync(0xffffffffu, s0, 1);
        s1 += __shfl_xor_sync(0xffffffffu, s1, 1);
        s2 += __shfl_xor_sync(0xffffffffu, s2, 1);
        s3 += __shfl_xor_sync(0xffffffffu, s3, 1);
        s0 += __shfl_xor_sync(0xffffffffu, s0, 2);
        s1 += __shfl_xor_sync(0xffffffffu, s1, 2);
        s2 += __shfl_xor_sync(0xffffffffu, s2, 2);
        s3 += __shfl_xor_sync(0xffffffffu, s3, 2);
        float ex0 = __expf(s0 * 0.25f);
        float ex1 = __expf(s1 * 0.25f);
        float ex2 = __expf(s2 * 0.25f);
        float ex3 = __expf(s3 * 0.25f);
        den += (ex0 + ex1) + (ex2 + ex3);
        acc.x += ex0 * v0.x + ex1 * v1.x + ex2 * v2.x + ex3 * v3.x;
        acc.y += ex0 * v0.y + ex1 * v1.y + ex2 * v2.y + ex3 * v3.y;
        acc.z += ex0 * v0.z + ex1 * v1.z + ex2 * v2.z + ex3 * v3.z;
        acc.w += ex0 * v0.w + ex1 * v1.w + ex2 * v2.w + ex3 * v3.w;
    }
    for (; j < end; j++) {
        int kn = g_kn[j];
        float4 k4 = ld_half4(g_Kh + (size_t)kn * HH + lane * 4);
        float4 v4 = ld_half4(g_Vh + (size_t)kn * HH + lane * 4);
        float s = qv.x * k4.x + qv.y * k4.y + qv.z * k4.z + qv.w * k4.w;
        s += __shfl_xor_sync(0xffffffffu, s, 1);
        s += __shfl_xor_sync(0xffffffffu, s, 2);
        float ex = __expf(s * 0.25f);
        den += ex;
        acc.x += ex * v4.x;
        acc.y += ex * v4.y;
        acc.z += ex * v4.z;
        acc.w += ex * v4.w;
    }

    float inv = (end > beg) ? (1.f / den) : 0.f;
    float4 o = make_float4(acc.x * inv, acc.y * inv, acc.z * inv, acc.w * inv);
    ((float4*)(out + (size_t)i * HH))[lane] = o;
}

// ---------------- launch ----------------
extern "C" void kernel_launch(void* const* d_in, const int* in_sizes, int n_in,
                              void* d_out, int out_size) {
    const float* q = (const float*)d_in[0];
    const float* k = (const float*)d_in[1];
    const float* v = (const float*)d_in[2];
    const float* Wq = (const float*)d_in[3];
    const float* bq = (const float*)d_in[4];
    const float* Wk = (const float*)d_in[5];
    const float* bk = (const float*)d_in[6];
    const float* Wv = (const float*)d_in[7];
    const float* bv = (const float*)d_in[8];
    const int* qi = (const int*)d_in[9];
    const int* ki = (const int*)d_in[10];

    int Nn = in_sizes[0] / HH;   // 50000
    int E = in_sizes[9];         // 800000
    float* out = (float*)d_out;

    // One-time host-side resources (no device memory involved).
    static cudaStream_t s2 = nullptr;
    static cudaEvent_t evFork = nullptr, evJoin = nullptr;
    if (s2 == nullptr) {
        cudaStreamCreateWithFlags(&s2, cudaStreamNonBlocking);
        cudaEventCreateWithFlags(&evFork, cudaEventDisableTiming);
        cudaEventCreateWithFlags(&evJoin, cudaEventDisableTiming);
        cudaFuncSetAttribute(proj_mma,
                             cudaFuncAttributeMaxDynamicSharedMemorySize,
                             SM_GEMM_TOTAL);
    }

    // ---- fork: projection branch runs concurrently with CSR build ----
    cudaEventRecord(evFork, 0);
    cudaStreamWaitEvent(s2, evFork, 0);

    // Branch B (stream s2): per-node projections on HMMA (split-bf16)
    proj_mma<<<dim3((Nn + GBM - 1) / GBM, 1, 3), 256, SM_GEMM_TOTAL, s2>>>(
        q, k, v, Wq, Wk, Wv, bq, bk, bv, Nn);
    cudaEventRecord(evJoin, s2);

    // Branch A (origin stream): CSR build over destination nodes
    int nb = (Nn + SCAN_BLK - 1) / SCAN_BLK;     // 49 for N=50000
    zero_kernel<<<(Nn + 255) / 256, 256>>>(Nn);
    hist_kernel<<<(E + 255) / 256, 256>>>(qi, E);
    scan1_kernel<<<nb, SCAN_BLK>>>(Nn);
    scan2_kernel<<<1, MAX_SCAN_BLOCKS>>>(nb, Nn);
    scan3_kernel<<<nb, SCAN_BLK>>>(Nn);
    scatter_kernel<<<(E + 255) / 256, 256>>>(qi, ki, E);

    // ---- join: attention needs both branches ----
    cudaStreamWaitEvent(0, evJoin, 0);

    // fused gather + scores + softmax + aggregate
    attn_kernel<<<((long long)Nn * 32 + 255) / 256, 256>>>(out, Nn);
}